// round 14
// baseline (speedup 1.0000x reference)
#include <cuda_runtime.h>
#include <cuda_fp16.h>
#include <cstdint>

#define N_NODES 50000
#define FIN     32
#define FOUT    64
#define KPTS    125
#define KROW    4032              /* 126 chunks * 32 : per-node A row   */
#define NCHUNK  126
#define NDCH    63                /* double-chunks of 64 columns        */
#define KSPLIT  4
#define DPG     16                /* double-chunks per K-group          */
#define E_MAX   900000
#define NPB     16                /* nodes per scatter block            */

/* 403 MB fp16 scratch: per node [125 spline chunks | 1 root chunk] x 32 */
__device__ __half g_T[(size_t)N_NODES * KROW];
__device__ int    g_degi[N_NODES];
__device__ int    g_rowoff[N_NODES + 1];
__device__ int    g_cursor[N_NODES];
__device__ int    g_eidx[E_MAX];
/* fragment-ordered fp16 weights: [252 ksteps][8 ntiles][32 lanes] x uint2 */
__device__ uint2  g_Wfrag[NCHUNK * 2 * 8 * 32];
/* split-K partial outputs: [KSPLIT][N][64] fp32 (51 MB) */
__device__ float  g_part[(size_t)KSPLIT * N_NODES * FOUT];

/* ------------------------------------------------------------------ */
__global__ void wfrag_kernel(const float* __restrict__ W) {
    int t = blockIdx.x * blockDim.x + threadIdx.x;
    if (t >= NCHUNK * 2 * 8 * 32) return;
    int lane = t & 31;
    int j    = (t >> 5) & 7;
    int ks   = (t >> 8) & 1;
    int ch   = t >> 9;
    int n  = j * 8 + (lane >> 2);
    int k0 = ch * 32 + ks * 16 + (lane & 3) * 2;
    __half2 r0 = __floats2half2_rn(W[(size_t)k0 * 64 + n],
                                   W[(size_t)(k0 + 1) * 64 + n]);
    __half2 r1 = __floats2half2_rn(W[(size_t)(k0 + 8) * 64 + n],
                                   W[(size_t)(k0 + 9) * 64 + n]);
    g_Wfrag[t] = make_uint2(*(unsigned*)&r0, *(unsigned*)&r1);
}

/* ------------------------------------------------------------------ */
/* CSR build                                                          */
__global__ void count_kernel(const int* __restrict__ ei, long E) {
    long e = (long)blockIdx.x * blockDim.x + threadIdx.x;
    if (e < E) atomicAdd(&g_degi[ei[e]], 1);
}

__global__ void scan_kernel() {
    __shared__ int sh[1024];
    __shared__ int s_run;
    int t = threadIdx.x;
    if (t == 0) s_run = 0;
    __syncthreads();
    for (int base = 0; base < N_NODES; base += 1024) {
        int idx = base + t;
        int v = (idx < N_NODES) ? g_degi[idx] : 0;
        sh[t] = v;
        __syncthreads();
        for (int off = 1; off < 1024; off <<= 1) {
            int add = (t >= off) ? sh[t - off] : 0;
            __syncthreads();
            sh[t] += add;
            __syncthreads();
        }
        if (idx < N_NODES) {
            int excl = s_run + sh[t] - v;
            g_rowoff[idx] = excl;
            g_cursor[idx] = excl;
        }
        __syncthreads();
        if (t == 0) s_run += sh[1023];
        __syncthreads();
    }
    if (t == 0) g_rowoff[N_NODES] = s_run;
}

__global__ void fill_kernel(const int* __restrict__ ei, long E) {
    long e = (long)blockIdx.x * blockDim.x + threadIdx.x;
    if (e >= E) return;
    int p = atomicAdd(&g_cursor[ei[e]], 1);
    g_eidx[p] = (int)e;
}

/* ------------------------------------------------------------------ */
/* Block-owned scatter: block owns NPB=16 nodes. Zero rows, then      */
/* edge-parallel red.global into L2-resident block-private region,    */
/* then root-chunk fill. No global memset, no cross-block races.      */
__global__ void __launch_bounds__(256)
scatter_block_kernel(const float* __restrict__ x,
                     const int* __restrict__ ei,
                     const float* __restrict__ pseudo,
                     long E)
{
    int tid = threadIdx.x;
    int n0  = blockIdx.x * NPB;

    /* zero the 16 owned rows: 16*KROW/8 = 8064 uint4, 32 per thread */
    uint4* base4 = (uint4*)(g_T + (size_t)n0 * KROW);
    uint4  z = make_uint4(0, 0, 0, 0);
#pragma unroll 8
    for (int i = tid; i < NPB * KROW / 8; i += 256) base4[i] = z;
    __syncthreads();

    int i0 = g_rowoff[n0];
    int i1 = g_rowoff[n0 + NPB];

    /* edge-parallel: tasks = (edge, quad); strided over the block */
    for (int t = i0 * 4 + tid; t < i1 * 4; t += 256) {
        int e   = g_eidx[t >> 2];
        int q   = t & 3;
        int dst = ei[e];             /* in [n0, n0+NPB) by CSR        */
        int src = ei[E + e];

        float p0 = pseudo[e * 3 + 0] * 4.0f;
        float p1 = pseudo[e * 3 + 1] * 4.0f;
        float p2 = pseudo[e * 3 + 2] * 4.0f;
        const float4 xa = *(const float4*)(x + (size_t)src * FIN + q * 8);
        const float4 xb = *(const float4*)(x + (size_t)src * FIN + q * 8 + 4);

        float f0 = floorf(p0), f1 = floorf(p1), f2 = floorf(p2);
        float r0 = p0 - f0,    r1 = p1 - f1,    r2 = p2 - f2;
        int   i0c = (int)f0,   i1c = (int)f1,   i2c = (int)f2;

        __half* Tb = g_T + (size_t)dst * KROW + q * 8;

#pragma unroll
        for (int s = 0; s < 8; ++s) {
            int   b0 = s & 1, b1 = (s >> 1) & 1, b2 = (s >> 2) & 1;
            float basis = (b0 ? r0 : 1.0f - r0)
                        * (b1 ? r1 : 1.0f - r1)
                        * (b2 ? r2 : 1.0f - r2);
            int c0 = i0c + b0; if (c0 >= 5) c0 -= 5;
            int c1 = i1c + b1; if (c1 >= 5) c1 -= 5;
            int c2 = i2c + b2; if (c2 >= 5) c2 -= 5;
            int wi = c0 + 5 * c1 + 25 * c2;

            __half2 v0 = __floats2half2_rn(basis * xa.x, basis * xa.y);
            __half2 v1 = __floats2half2_rn(basis * xa.z, basis * xa.w);
            __half2 v2 = __floats2half2_rn(basis * xb.x, basis * xb.y);
            __half2 v3 = __floats2half2_rn(basis * xb.z, basis * xb.w);

            __half* ptr = Tb + (size_t)wi * FIN;
            asm volatile("red.global.add.noftz.v4.f16x2 [%0], {%1,%2,%3,%4};"
                         :: "l"(ptr),
                            "r"(*(unsigned*)&v0), "r"(*(unsigned*)&v1),
                            "r"(*(unsigned*)&v2), "r"(*(unsigned*)&v3)
                         : "memory");
        }
    }

    /* root chunk: untouched by reds (wi<=124), no sync needed */
    if (tid < NPB * 4) {
        int n  = n0 + (tid >> 2);
        int cv = tid & 3;
        float dg = fmaxf((float)(g_rowoff[n + 1] - g_rowoff[n]), 1.0f);
        float4 a = *(const float4*)(x + (size_t)n * FIN + cv * 8);
        float4 b = *(const float4*)(x + (size_t)n * FIN + cv * 8 + 4);
        __half2 p0 = __floats2half2_rn(a.x * dg, a.y * dg);
        __half2 p1 = __floats2half2_rn(a.z * dg, a.w * dg);
        __half2 p2 = __floats2half2_rn(b.x * dg, b.y * dg);
        __half2 p3 = __floats2half2_rn(b.z * dg, b.w * dg);
        *(uint4*)(g_T + (size_t)n * KROW + KPTS * FIN + cv * 8) =
            make_uint4(*(unsigned*)&p0, *(unsigned*)&p1,
                       *(unsigned*)&p2, *(unsigned*)&p3);
    }
}

/* ------------------------------------------------------------------ */
/* fp16 TC GEMM (R11): split-K x4, 64-col double-chunk 2-stage ring,  */
/* register-tiled M: 128 threads, warp owns 32 rows.                  */

#define BM     128
#define DS     72
#define ATILE2 (BM * DS)

__device__ __forceinline__ void cp_async16(__half* smem_dst, const __half* gsrc) {
    unsigned s = (unsigned)__cvta_generic_to_shared(smem_dst);
    asm volatile("cp.async.cg.shared.global [%0], [%1], 16;" :: "r"(s), "l"(gsrc));
}

__device__ __forceinline__ void mma_f16(float* d, const unsigned* a, const unsigned* b) {
    asm volatile("mma.sync.aligned.m16n8k16.row.col.f32.f16.f16.f32 "
                 "{%0,%1,%2,%3}, {%4,%5,%6,%7}, {%8,%9}, {%0,%1,%2,%3};"
                 : "+f"(d[0]), "+f"(d[1]), "+f"(d[2]), "+f"(d[3])
                 : "r"(a[0]), "r"(a[1]), "r"(a[2]), "r"(a[3]),
                   "r"(b[0]), "r"(b[1]));
}

__global__ void __launch_bounds__(128, 4)
gemm_kernel(void)
{
    __shared__ __half As[2 * ATILE2];

    int tid  = threadIdx.x;
    int warp = tid >> 5;
    int lane = tid & 31;
    int m0   = blockIdx.x * BM;
    int grp  = blockIdx.y;
    int d0   = grp * DPG;
    int d1   = d0 + DPG; if (d1 > NDCH) d1 = NDCH;

    int nc = m0 + tid; if (nc >= N_NODES) nc = N_NODES - 1;
    const __half* srcA = g_T + (size_t)nc * KROW;
    __half*       dstA = As + tid * DS;

    float acc0[8][4], acc1[8][4];
#pragma unroll
    for (int j = 0; j < 8; ++j)
#pragma unroll
        for (int i = 0; i < 4; ++i) { acc0[j][i] = 0.f; acc1[j][i] = 0.f; }

#pragma unroll
    for (int i = 0; i < 8; ++i)
        cp_async16(dstA + (d0 & 1) * ATILE2 + i * 8, srcA + (size_t)d0 * 64 + i * 8);
    asm volatile("cp.async.commit_group;");

    int ar0 = warp * 32 + (lane >> 2);
    int ar1 = ar0 + 16;
    int ac  = (lane & 3) * 2;

    for (int d = d0; d < d1; ++d) {
        if (d + 1 < d1) {
            __half*       dn = dstA + ((d + 1) & 1) * ATILE2;
            const __half* sn = srcA + (size_t)(d + 1) * 64;
#pragma unroll
            for (int i = 0; i < 8; ++i)
                cp_async16(dn + i * 8, sn + i * 8);
        }
        asm volatile("cp.async.commit_group;");
        asm volatile("cp.async.wait_group 1;");
        __syncthreads();

        const __half* A = As + (d & 1) * ATILE2;
        const uint2*  wfd = g_Wfrag + (size_t)(4 * d) * 256 + lane;
#pragma unroll
        for (int ks = 0; ks < 4; ++ks) {
            int c = ks * 16 + ac;
            unsigned a0[4], a1[4];
            a0[0] = *(const unsigned*)(A + ar0 * DS + c);
            a0[1] = *(const unsigned*)(A + (ar0 + 8) * DS + c);
            a0[2] = *(const unsigned*)(A + ar0 * DS + c + 8);
            a0[3] = *(const unsigned*)(A + (ar0 + 8) * DS + c + 8);
            a1[0] = *(const unsigned*)(A + ar1 * DS + c);
            a1[1] = *(const unsigned*)(A + (ar1 + 8) * DS + c);
            a1[2] = *(const unsigned*)(A + ar1 * DS + c + 8);
            a1[3] = *(const unsigned*)(A + (ar1 + 8) * DS + c + 8);
            const uint2* wf = wfd + (size_t)ks * 256;
#pragma unroll
            for (int j = 0; j < 8; ++j) {
                uint2 bv = wf[j * 32];
                unsigned b[2] = { bv.x, bv.y };
                mma_f16(acc0[j], a0, b);
                mma_f16(acc1[j], a1, b);
            }
        }
        __syncthreads();
    }

    float* part = g_part + (size_t)grp * N_NODES * FOUT;
    int r  = lane >> 2;
    int cp = (lane & 3) * 2;
#pragma unroll
    for (int m = 0; m < 2; ++m) {
        float (*acc)[4] = m ? acc1 : acc0;
        int n0 = m0 + warp * 32 + m * 16 + r;
#pragma unroll
        for (int j = 0; j < 8; ++j) {
            int col = j * 8 + cp;
            if (n0 < N_NODES) {
                float dg = fmaxf((float)g_degi[n0], 1.0f);
                part[(size_t)n0 * FOUT + col]     = acc[j][0] / dg;
                part[(size_t)n0 * FOUT + col + 1] = acc[j][1] / dg;
            }
            if (n0 + 8 < N_NODES) {
                float dg = fmaxf((float)g_degi[n0 + 8], 1.0f);
                part[(size_t)(n0 + 8) * FOUT + col]     = acc[j][2] / dg;
                part[(size_t)(n0 + 8) * FOUT + col + 1] = acc[j][3] / dg;
            }
        }
    }
}

/* ------------------------------------------------------------------ */
__global__ void reduce_kernel(const float* __restrict__ bias,
                              float* __restrict__ out)
{
    int t = blockIdx.x * blockDim.x + threadIdx.x;
    if (t >= N_NODES * FOUT / 4) return;
    const size_t stride = (size_t)N_NODES * FOUT / 4;
    const float4* p = (const float4*)g_part;
    float4 a = p[t];
    float4 b = p[t + stride];
    float4 c = p[t + 2 * stride];
    float4 d = p[t + 3 * stride];
    int col = (t & 15) * 4;
    float4 o;
    o.x = a.x + b.x + c.x + d.x + bias[col];
    o.y = a.y + b.y + c.y + d.y + bias[col + 1];
    o.z = a.z + b.z + c.z + d.z + bias[col + 2];
    o.w = a.w + b.w + c.w + d.w + bias[col + 3];
    ((float4*)out)[t] = o;
}

/* ------------------------------------------------------------------ */
extern "C" void kernel_launch(void* const* d_in, const int* in_sizes, int n_in,
                              void* d_out, int out_size)
{
    const float* x      = (const float*)d_in[0];
    const int*   ei     = (const int*)d_in[1];
    const float* pseudo = (const float*)d_in[2];
    const float* weight = (const float*)d_in[3];   /* [126,32,64] */
    const float* bias   = (const float*)d_in[4];
    float*       out    = (float*)d_out;

    long E = (long)in_sizes[1] / 2;

    void* Dptr;
    cudaGetSymbolAddress(&Dptr, g_degi);

    /* repack weights (tiny) */
    wfrag_kernel<<<(NCHUNK * 2 * 8 * 32 + 255) / 256, 256>>>(weight);

    /* CSR build */
    cudaMemsetAsync(Dptr, 0, N_NODES * sizeof(int), 0);
    count_kernel<<<(int)((E + 255) / 256), 256>>>(ei, E);
    scan_kernel<<<1, 1024>>>();
    fill_kernel<<<(int)((E + 255) / 256), 256>>>(ei, E);

    /* block-owned scatter: zero + red + rootfill, no global memset */
    scatter_block_kernel<<<N_NODES / NPB, 256>>>(x, ei, pseudo, E);

    /* split-K GEMM -> partials, then reduce(+bias) */
    {
        dim3 grid((N_NODES + BM - 1) / BM, KSPLIT);
        gemm_kernel<<<grid, 128>>>();
        reduce_kernel<<<(N_NODES * FOUT / 4 + 255) / 256, 256>>>(bias, out);
    }
}

// round 15
// speedup vs baseline: 1.2501x; 1.2501x over previous
#include <cuda_runtime.h>
#include <cuda_fp16.h>
#include <cstdint>

#define N_NODES 50000
#define FIN     32
#define FOUT    64
#define KPTS    125
#define NCHUNK  126
#define NDCH    63                /* 64-half double-chunks              */
#define KSPLIT  3
#define DPG     21                /* 63 = 3 * 21                        */
#define BM      128

/* chunk-major, SW-swizzled scratch: [63 planes][N nodes][64 halfs]    */
/* + 128 pad rows so the last tile's bulk read stays in bounds         */
#define T_HALFS ((size_t)NDCH * N_NODES * 64 + 128 * 64)
__device__ __half g_T[T_HALFS];
__device__ float  g_deg[N_NODES];
/* fragment-ordered fp16 weights: [252 ksteps][8 ntiles][32 lanes] x uint2 */
__device__ uint2  g_Wfrag[NCHUNK * 2 * 8 * 32];
/* split-K partial outputs: [KSPLIT][N][64] fp32 */
__device__ float  g_part[(size_t)KSPLIT * N_NODES * FOUT];

/* ------------------------------------------------------------------ */
__global__ void wfrag_kernel(const float* __restrict__ W) {
    int t = blockIdx.x * blockDim.x + threadIdx.x;
    if (t >= NCHUNK * 2 * 8 * 32) return;
    int lane = t & 31;
    int j    = (t >> 5) & 7;
    int ks   = (t >> 8) & 1;
    int ch   = t >> 9;
    int n  = j * 8 + (lane >> 2);
    int k0 = ch * 32 + ks * 16 + (lane & 3) * 2;
    __half2 r0 = __floats2half2_rn(W[(size_t)k0 * 64 + n],
                                   W[(size_t)(k0 + 1) * 64 + n]);
    __half2 r1 = __floats2half2_rn(W[(size_t)(k0 + 8) * 64 + n],
                                   W[(size_t)(k0 + 9) * 64 + n]);
    g_Wfrag[t] = make_uint2(*(unsigned*)&r0, *(unsigned*)&r1);
}

/* ------------------------------------------------------------------ */
/* Scatter: 4 lanes/edge, red.v4.f16x2 into chunk-major swizzled T.   */
__global__ void __launch_bounds__(256)
scatter_kernel(const float* __restrict__ x,
               const int* __restrict__ ei,
               const float* __restrict__ pseudo,
               long E)
{
    long t    = (long)blockIdx.x * blockDim.x + threadIdx.x;
    int  q    = (int)(t & 3);
    long e    = t >> 2;
    if (e >= E) return;

    int dst = ei[e];
    int src = ei[E + e];

    float p0 = pseudo[e * 3 + 0] * 4.0f;
    float p1 = pseudo[e * 3 + 1] * 4.0f;
    float p2 = pseudo[e * 3 + 2] * 4.0f;
    float f0 = floorf(p0), f1 = floorf(p1), f2 = floorf(p2);
    float r0 = p0 - f0,    r1 = p1 - f1,    r2 = p2 - f2;
    int   i0 = (int)f0,    i1 = (int)f1,    i2 = (int)f2;

    const float4 xa = *(const float4*)(x + (size_t)src * FIN + q * 8);
    const float4 xb = *(const float4*)(x + (size_t)src * FIN + q * 8 + 4);

    if (q == 0) atomicAdd(&g_deg[dst], 1.0f);

    int     sw   = dst & 7;
    __half* base = g_T + (size_t)dst * 64;
    const size_t PL = (size_t)N_NODES * 64;

#pragma unroll
    for (int s = 0; s < 8; ++s) {
        int   b0 = s & 1, b1 = (s >> 1) & 1, b2 = (s >> 2) & 1;
        float basis = (b0 ? r0 : 1.0f - r0)
                    * (b1 ? r1 : 1.0f - r1)
                    * (b2 ? r2 : 1.0f - r2);
        int c0 = i0 + b0; if (c0 >= 5) c0 -= 5;
        int c1 = i1 + b1; if (c1 >= 5) c1 -= 5;
        int c2 = i2 + b2; if (c2 >= 5) c2 -= 5;
        int wi = c0 + 5 * c1 + 25 * c2;

        __half2 v0 = __floats2half2_rn(basis * xa.x, basis * xa.y);
        __half2 v1 = __floats2half2_rn(basis * xa.z, basis * xa.w);
        __half2 v2 = __floats2half2_rn(basis * xb.x, basis * xb.y);
        __half2 v3 = __floats2half2_rn(basis * xb.z, basis * xb.w);

        int su = (((wi & 1) << 2) + q) ^ sw;
        __half* ptr = base + (size_t)(wi >> 1) * PL + su * 8;
        asm volatile("red.global.add.noftz.v4.f16x2 [%0], {%1,%2,%3,%4};"
                     :: "l"(ptr),
                        "r"(*(unsigned*)&v0), "r"(*(unsigned*)&v1),
                        "r"(*(unsigned*)&v2), "r"(*(unsigned*)&v3)
                     : "memory");
    }
}

/* ------------------------------------------------------------------ */
/* Root-chunk fill: wi=125 -> plane 62, upper 64B half; swizzled.     */
__global__ void rootfill_kernel(const float* __restrict__ x) {
    int t = blockIdx.x * blockDim.x + threadIdx.x;
    if (t >= N_NODES * 4) return;
    int n = t >> 2, cv = t & 3;
    float dg = fmaxf(g_deg[n], 1.0f);
    float4 a = *(const float4*)(x + (size_t)n * FIN + cv * 8);
    float4 b = *(const float4*)(x + (size_t)n * FIN + cv * 8 + 4);
    __half2 p0 = __floats2half2_rn(a.x * dg, a.y * dg);
    __half2 p1 = __floats2half2_rn(a.z * dg, a.w * dg);
    __half2 p2 = __floats2half2_rn(b.x * dg, b.y * dg);
    __half2 p3 = __floats2half2_rn(b.z * dg, b.w * dg);
    int su = (4 + cv) ^ (n & 7);
    *(uint4*)(g_T + ((size_t)62 * N_NODES + n) * 64 + su * 8) =
        make_uint4(*(unsigned*)&p0, *(unsigned*)&p1,
                   *(unsigned*)&p2, *(unsigned*)&p3);
}

/* ------------------------------------------------------------------ */
/* fp16 TC GEMM: split-K x3, A via cp.async.bulk (1 instr / 16KB),    */
/* mbarrier complete_tx, swizzled conflict-free LDS, warp = 32 rows.  */

__device__ __forceinline__ uint32_t smem_u32(const void* p) {
    uint32_t a;
    asm("{ .reg .u64 t; cvta.to.shared.u64 t, %1; cvt.u32.u64 %0, t; }"
        : "=r"(a) : "l"(p));
    return a;
}
__device__ __forceinline__ void mbar_wait(uint32_t mbar, uint32_t parity) {
    asm volatile("{\n\t.reg .pred P;\n\t"
                 "WL_%=:\n\t"
                 "mbarrier.try_wait.parity.acquire.cta.shared::cta.b64 P, [%0], %1, 0x989680;\n\t"
                 "@P bra.uni WD_%=;\n\t"
                 "bra.uni WL_%=;\n\t"
                 "WD_%=:\n\t}"
                 :: "r"(mbar), "r"(parity) : "memory");
}
__device__ __forceinline__ void mma_f16(float* d, const unsigned* a, const unsigned* b) {
    asm volatile("mma.sync.aligned.m16n8k16.row.col.f32.f16.f16.f32 "
                 "{%0,%1,%2,%3}, {%4,%5,%6,%7}, {%8,%9}, {%0,%1,%2,%3};"
                 : "+f"(d[0]), "+f"(d[1]), "+f"(d[2]), "+f"(d[3])
                 : "r"(a[0]), "r"(a[1]), "r"(a[2]), "r"(a[3]),
                   "r"(b[0]), "r"(b[1]));
}

__global__ void __launch_bounds__(128, 4)
gemm_kernel(void)
{
    __shared__ alignas(128) __half As[2 * 8192];   /* 2 x 16KB stages */
    __shared__ uint64_t mbars[2];

    int tid  = threadIdx.x;
    int warp = tid >> 5;
    int lane = tid & 31;
    int m0   = blockIdx.x * BM;
    int t0   = blockIdx.y * DPG;

    if (tid == 0) {
        asm volatile("mbarrier.init.shared.b64 [%0], 1;"
                     :: "r"(smem_u32(&mbars[0])) : "memory");
        asm volatile("mbarrier.init.shared.b64 [%0], 1;"
                     :: "r"(smem_u32(&mbars[1])) : "memory");
    }
    __syncthreads();

    uint32_t mb0 = smem_u32(&mbars[0]);
    uint32_t mb1 = smem_u32(&mbars[1]);
    uint32_t sA  = smem_u32(As);

    auto ISSUE = [&](int t) {
        if (tid == 0) {
            uint32_t mbar = (t & 1) ? mb1 : mb0;
            uint32_t dst  = sA + (t & 1) * 16384;
            const __half* src = g_T + ((size_t)(t0 + t) * N_NODES + m0) * 64;
            asm volatile("mbarrier.arrive.expect_tx.shared.b64 _, [%0], %1;"
                         :: "r"(mbar), "r"(16384u) : "memory");
            asm volatile("cp.async.bulk.shared::cluster.global.mbarrier::complete_tx::bytes "
                         "[%0], [%1], %2, [%3];"
                         :: "r"(dst), "l"(src), "r"(16384u), "r"(mbar)
                         : "memory");
        }
    };

    ISSUE(0);
    ISSUE(1);

    float acc0[8][4], acc1[8][4];
#pragma unroll
    for (int j = 0; j < 8; ++j)
#pragma unroll
        for (int i = 0; i < 4; ++i) { acc0[j][i] = 0.f; acc1[j][i] = 0.f; }

    int rx  = warp * 32 + (lane >> 2);     /* m-tile0 base row         */
    int sw  = (lane >> 2) & 7;             /* swizzle key (same +8/+16/+24) */
    int sub = (lane & 3) * 4;              /* byte sub-offset in unit  */

    for (int t = 0; t < DPG; ++t) {
        uint32_t mbar = (t & 1) ? mb1 : mb0;
        mbar_wait(mbar, (t >> 1) & 1);

        const char* A = (const char*)As + (t & 1) * 16384;
        const uint2* wfd = g_Wfrag + (size_t)(4 * (t0 + t)) * 256 + lane;
#pragma unroll
        for (int ks = 0; ks < 4; ++ks) {
            int o0 = (((ks * 2)     ^ sw) << 4) + sub;
            int o1 = (((ks * 2 + 1) ^ sw) << 4) + sub;
            unsigned a0[4], a1[4];
            a0[0] = *(const unsigned*)(A + (rx     ) * 128 + o0);
            a0[1] = *(const unsigned*)(A + (rx +  8) * 128 + o0);
            a0[2] = *(const unsigned*)(A + (rx     ) * 128 + o1);
            a0[3] = *(const unsigned*)(A + (rx +  8) * 128 + o1);
            a1[0] = *(const unsigned*)(A + (rx + 16) * 128 + o0);
            a1[1] = *(const unsigned*)(A + (rx + 24) * 128 + o0);
            a1[2] = *(const unsigned*)(A + (rx + 16) * 128 + o1);
            a1[3] = *(const unsigned*)(A + (rx + 24) * 128 + o1);
            const uint2* wf = wfd + (size_t)ks * 256;
#pragma unroll
            for (int j = 0; j < 8; ++j) {
                uint2 bv = wf[j * 32];
                unsigned b[2] = { bv.x, bv.y };
                mma_f16(acc0[j], a0, b);
                mma_f16(acc1[j], a1, b);
            }
        }
        __syncthreads();
        if (t + 2 < DPG) {
            if (tid == 0)
                asm volatile("fence.proxy.async.shared::cta;" ::: "memory");
            ISSUE(t + 2);
        }
    }

    /* ---- epilogue: /deg, store partial ---- */
    float* part = g_part + (size_t)blockIdx.y * N_NODES * FOUT;
    int r  = lane >> 2;
    int cp = (lane & 3) * 2;
#pragma unroll
    for (int m = 0; m < 2; ++m) {
        float (*acc)[4] = m ? acc1 : acc0;
        int n0 = m0 + warp * 32 + m * 16 + r;
#pragma unroll
        for (int j = 0; j < 8; ++j) {
            int col = j * 8 + cp;
            if (n0 < N_NODES) {
                float dg = fmaxf(g_deg[n0], 1.0f);
                part[(size_t)n0 * FOUT + col]     = acc[j][0] / dg;
                part[(size_t)n0 * FOUT + col + 1] = acc[j][1] / dg;
            }
            if (n0 + 8 < N_NODES) {
                float dg = fmaxf(g_deg[n0 + 8], 1.0f);
                part[(size_t)(n0 + 8) * FOUT + col]     = acc[j][2] / dg;
                part[(size_t)(n0 + 8) * FOUT + col + 1] = acc[j][3] / dg;
            }
        }
    }
}

/* ------------------------------------------------------------------ */
/* Reduce: out = sum of 3 partials + bias                             */
__global__ void reduce_kernel(const float* __restrict__ bias,
                              float* __restrict__ out)
{
    int t = blockIdx.x * blockDim.x + threadIdx.x;
    if (t >= N_NODES * FOUT / 4) return;
    const size_t stride = (size_t)N_NODES * FOUT / 4;
    const float4* p = (const float4*)g_part;
    float4 a = p[t];
    float4 b = p[t + stride];
    float4 c = p[t + 2 * stride];
    int col = (t & 15) * 4;
    float4 o;
    o.x = a.x + b.x + c.x + bias[col];
    o.y = a.y + b.y + c.y + bias[col + 1];
    o.z = a.z + b.z + c.z + bias[col + 2];
    o.w = a.w + b.w + c.w + bias[col + 3];
    ((float4*)out)[t] = o;
}

/* ------------------------------------------------------------------ */
extern "C" void kernel_launch(void* const* d_in, const int* in_sizes, int n_in,
                              void* d_out, int out_size)
{
    const float* x      = (const float*)d_in[0];
    const int*   ei     = (const int*)d_in[1];
    const float* pseudo = (const float*)d_in[2];
    const float* weight = (const float*)d_in[3];   /* [126,32,64] */
    const float* bias   = (const float*)d_in[4];
    float*       out    = (float*)d_out;

    long E = (long)in_sizes[1] / 2;

    void *Tptr, *Dptr;
    cudaGetSymbolAddress(&Tptr, g_T);
    cudaGetSymbolAddress(&Dptr, g_deg);

    /* repack weights (tiny) */
    wfrag_kernel<<<(NCHUNK * 2 * 8 * 32 + 255) / 256, 256>>>(weight);

    /* zero T (incl. pad) and deg */
    cudaMemsetAsync(Tptr, 0, T_HALFS * sizeof(__half), 0);
    cudaMemsetAsync(Dptr, 0, (size_t)N_NODES * sizeof(float), 0);

    /* scatter */
    {
        long threads = E * 4;
        int blocks = (int)((threads + 255) / 256);
        scatter_kernel<<<blocks, 256>>>(x, ei, pseudo, E);
    }

    /* root chunk: x * deg */
    rootfill_kernel<<<(N_NODES * 4 + 255) / 256, 256>>>(x);

    /* split-K GEMM -> partials, then reduce(+bias) */
    {
        dim3 grid((N_NODES + BM - 1) / BM, KSPLIT);
        gemm_kernel<<<grid, 128>>>();
        reduce_kernel<<<(N_NODES * FOUT / 4 + 255) / 256, 256>>>(bias, out);
    }
}

// round 17
// speedup vs baseline: 1.2702x; 1.0160x over previous
#include <cuda_runtime.h>
#include <cuda_fp16.h>
#include <cstdint>

#define N_NODES 50000
#define FIN     32
#define FOUT    64
#define KPTS    125
#define NCHUNK  126
#define NDCH    63                /* 64-half double-chunks              */
#define KSPLIT  3
#define DPG     21                /* 63 = 3 * 21                        */
#define BM      128
#define NSTG    3
#define GEMM_SMEM (NSTG * 16384 + 64)   /* stages + mbarriers (dynamic) */

/* chunk-major, SW-swizzled scratch: [63 planes][N nodes][64 halfs]    */
/* + 128 pad rows so the last tile's bulk read stays in bounds         */
#define T_HALFS ((size_t)NDCH * N_NODES * 64 + 128 * 64)
__device__ __half g_T[T_HALFS];
__device__ float  g_deg[N_NODES];
/* fragment-ordered fp16 weights: [252 ksteps][8 ntiles][32 lanes] x uint2 */
__device__ uint2  g_Wfrag[NCHUNK * 2 * 8 * 32];

/* ------------------------------------------------------------------ */
__global__ void wfrag_kernel(const float* __restrict__ W) {
    int t = blockIdx.x * blockDim.x + threadIdx.x;
    if (t >= NCHUNK * 2 * 8 * 32) return;
    int lane = t & 31;
    int j    = (t >> 5) & 7;
    int ks   = (t >> 8) & 1;
    int ch   = t >> 9;
    int n  = j * 8 + (lane >> 2);
    int k0 = ch * 32 + ks * 16 + (lane & 3) * 2;
    __half2 r0 = __floats2half2_rn(W[(size_t)k0 * 64 + n],
                                   W[(size_t)(k0 + 1) * 64 + n]);
    __half2 r1 = __floats2half2_rn(W[(size_t)(k0 + 8) * 64 + n],
                                   W[(size_t)(k0 + 9) * 64 + n]);
    g_Wfrag[t] = make_uint2(*(unsigned*)&r0, *(unsigned*)&r1);
}

/* ------------------------------------------------------------------ */
/* out = bias broadcast (GEMM epilogue reds accumulate onto this)     */
__global__ void biasinit_kernel(const float* __restrict__ bias,
                                float* __restrict__ out)
{
    int t = blockIdx.x * blockDim.x + threadIdx.x;
    if (t >= N_NODES * FOUT / 4) return;
    ((float4*)out)[t] = ((const float4*)bias)[t & 15];
}

/* ------------------------------------------------------------------ */
/* Scatter: 4 lanes/edge, red.v4.f16x2 into chunk-major swizzled T.   */
__global__ void __launch_bounds__(256)
scatter_kernel(const float* __restrict__ x,
               const int* __restrict__ ei,
               const float* __restrict__ pseudo,
               long E)
{
    long t    = (long)blockIdx.x * blockDim.x + threadIdx.x;
    int  q    = (int)(t & 3);
    long e    = t >> 2;
    if (e >= E) return;

    int dst = ei[e];
    int src = ei[E + e];

    float p0 = pseudo[e * 3 + 0] * 4.0f;
    float p1 = pseudo[e * 3 + 1] * 4.0f;
    float p2 = pseudo[e * 3 + 2] * 4.0f;
    float f0 = floorf(p0), f1 = floorf(p1), f2 = floorf(p2);
    float r0 = p0 - f0,    r1 = p1 - f1,    r2 = p2 - f2;
    int   i0 = (int)f0,    i1 = (int)f1,    i2 = (int)f2;

    const float4 xa = *(const float4*)(x + (size_t)src * FIN + q * 8);
    const float4 xb = *(const float4*)(x + (size_t)src * FIN + q * 8 + 4);

    if (q == 0) atomicAdd(&g_deg[dst], 1.0f);

    int     sw   = dst & 7;
    __half* base = g_T + (size_t)dst * 64;
    const size_t PL = (size_t)N_NODES * 64;

#pragma unroll
    for (int s = 0; s < 8; ++s) {
        int   b0 = s & 1, b1 = (s >> 1) & 1, b2 = (s >> 2) & 1;
        float basis = (b0 ? r0 : 1.0f - r0)
                    * (b1 ? r1 : 1.0f - r1)
                    * (b2 ? r2 : 1.0f - r2);
        int c0 = i0 + b0; if (c0 >= 5) c0 -= 5;
        int c1 = i1 + b1; if (c1 >= 5) c1 -= 5;
        int c2 = i2 + b2; if (c2 >= 5) c2 -= 5;
        int wi = c0 + 5 * c1 + 25 * c2;

        __half2 v0 = __floats2half2_rn(basis * xa.x, basis * xa.y);
        __half2 v1 = __floats2half2_rn(basis * xa.z, basis * xa.w);
        __half2 v2 = __floats2half2_rn(basis * xb.x, basis * xb.y);
        __half2 v3 = __floats2half2_rn(basis * xb.z, basis * xb.w);

        int su = (((wi & 1) << 2) + q) ^ sw;
        __half* ptr = base + (size_t)(wi >> 1) * PL + su * 8;
        asm volatile("red.global.add.noftz.v4.f16x2 [%0], {%1,%2,%3,%4};"
                     :: "l"(ptr),
                        "r"(*(unsigned*)&v0), "r"(*(unsigned*)&v1),
                        "r"(*(unsigned*)&v2), "r"(*(unsigned*)&v3)
                     : "memory");
    }
}

/* ------------------------------------------------------------------ */
/* Root-chunk fill: wi=125 -> plane 62, upper 64B half; swizzled.     */
__global__ void rootfill_kernel(const float* __restrict__ x) {
    int t = blockIdx.x * blockDim.x + threadIdx.x;
    if (t >= N_NODES * 4) return;
    int n = t >> 2, cv = t & 3;
    float dg = fmaxf(g_deg[n], 1.0f);
    float4 a = *(const float4*)(x + (size_t)n * FIN + cv * 8);
    float4 b = *(const float4*)(x + (size_t)n * FIN + cv * 8 + 4);
    __half2 p0 = __floats2half2_rn(a.x * dg, a.y * dg);
    __half2 p1 = __floats2half2_rn(a.z * dg, a.w * dg);
    __half2 p2 = __floats2half2_rn(b.x * dg, b.y * dg);
    __half2 p3 = __floats2half2_rn(b.z * dg, b.w * dg);
    int su = (4 + cv) ^ (n & 7);
    *(uint4*)(g_T + ((size_t)62 * N_NODES + n) * 64 + su * 8) =
        make_uint4(*(unsigned*)&p0, *(unsigned*)&p1,
                   *(unsigned*)&p2, *(unsigned*)&p3);
}

/* ------------------------------------------------------------------ */
/* fp16 TC GEMM: split-K x3, A via cp.async.bulk, 3-stage ring in     */
/* DYNAMIC smem, epilogue red.global.add.v2.f32 into out (bias set).  */

__device__ __forceinline__ uint32_t smem_u32(const void* p) {
    uint32_t a;
    asm("{ .reg .u64 t; cvta.to.shared.u64 t, %1; cvt.u32.u64 %0, t; }"
        : "=r"(a) : "l"(p));
    return a;
}
__device__ __forceinline__ void mbar_wait(uint32_t mbar, uint32_t parity) {
    asm volatile("{\n\t.reg .pred P;\n\t"
                 "WL_%=:\n\t"
                 "mbarrier.try_wait.parity.acquire.cta.shared::cta.b64 P, [%0], %1, 0x989680;\n\t"
                 "@P bra.uni WD_%=;\n\t"
                 "bra.uni WL_%=;\n\t"
                 "WD_%=:\n\t}"
                 :: "r"(mbar), "r"(parity) : "memory");
}
__device__ __forceinline__ void mma_f16(float* d, const unsigned* a, const unsigned* b) {
    asm volatile("mma.sync.aligned.m16n8k16.row.col.f32.f16.f16.f32 "
                 "{%0,%1,%2,%3}, {%4,%5,%6,%7}, {%8,%9}, {%0,%1,%2,%3};"
                 : "+f"(d[0]), "+f"(d[1]), "+f"(d[2]), "+f"(d[3])
                 : "r"(a[0]), "r"(a[1]), "r"(a[2]), "r"(a[3]),
                   "r"(b[0]), "r"(b[1]));
}

__global__ void __launch_bounds__(128, 4)
gemm_kernel(float* __restrict__ out)
{
    extern __shared__ __align__(128) unsigned char dynsm[];
    __half*   As    = (__half*)dynsm;                       /* 3 x 16KB */
    uint64_t* mbars = (uint64_t*)(dynsm + NSTG * 16384);    /* 3 mbar   */

    int tid  = threadIdx.x;
    int warp = tid >> 5;
    int lane = tid & 31;
    int m0   = blockIdx.x * BM;
    int t0   = blockIdx.y * DPG;

    if (tid == 0) {
#pragma unroll
        for (int s = 0; s < NSTG; ++s)
            asm volatile("mbarrier.init.shared.b64 [%0], 1;"
                         :: "r"(smem_u32(&mbars[s])) : "memory");
    }
    __syncthreads();

    uint32_t mb[NSTG];
#pragma unroll
    for (int s = 0; s < NSTG; ++s) mb[s] = smem_u32(&mbars[s]);
    uint32_t sA = smem_u32(As);

    auto ISSUE = [&](int t, int s) {
        if (tid == 0) {
            uint32_t dst = sA + s * 16384;
            const __half* src = g_T + ((size_t)(t0 + t) * N_NODES + m0) * 64;
            asm volatile("mbarrier.arrive.expect_tx.shared.b64 _, [%0], %1;"
                         :: "r"(mb[s]), "r"(16384u) : "memory");
            asm volatile("cp.async.bulk.shared::cluster.global.mbarrier::complete_tx::bytes "
                         "[%0], [%1], %2, [%3];"
                         :: "r"(dst), "l"(src), "r"(16384u), "r"(mb[s])
                         : "memory");
        }
    };

    ISSUE(0, 0);
    ISSUE(1, 1);
    ISSUE(2, 2);

    float acc0[8][4], acc1[8][4];
#pragma unroll
    for (int j = 0; j < 8; ++j)
#pragma unroll
        for (int i = 0; i < 4; ++i) { acc0[j][i] = 0.f; acc1[j][i] = 0.f; }

    int rx  = warp * 32 + (lane >> 2);
    int sw  = (lane >> 2) & 7;
    int sub = (lane & 3) * 4;

    int stage = 0, phase = 0;
    for (int t = 0; t < DPG; ++t) {
        mbar_wait(mb[stage], phase);

        const char* A = (const char*)As + stage * 16384;
        const uint2* wfd = g_Wfrag + (size_t)(4 * (t0 + t)) * 256 + lane;
#pragma unroll
        for (int ks = 0; ks < 4; ++ks) {
            int o0 = (((ks * 2)     ^ sw) << 4) + sub;
            int o1 = (((ks * 2 + 1) ^ sw) << 4) + sub;
            unsigned a0[4], a1[4];
            a0[0] = *(const unsigned*)(A + (rx     ) * 128 + o0);
            a0[1] = *(const unsigned*)(A + (rx +  8) * 128 + o0);
            a0[2] = *(const unsigned*)(A + (rx     ) * 128 + o1);
            a0[3] = *(const unsigned*)(A + (rx +  8) * 128 + o1);
            a1[0] = *(const unsigned*)(A + (rx + 16) * 128 + o0);
            a1[1] = *(const unsigned*)(A + (rx + 24) * 128 + o0);
            a1[2] = *(const unsigned*)(A + (rx + 16) * 128 + o1);
            a1[3] = *(const unsigned*)(A + (rx + 24) * 128 + o1);
            const uint2* wf = wfd + (size_t)ks * 256;
#pragma unroll
            for (int j = 0; j < 8; ++j) {
                uint2 bv = wf[j * 32];
                unsigned b[2] = { bv.x, bv.y };
                mma_f16(acc0[j], a0, b);
                mma_f16(acc1[j], a1, b);
            }
        }
        __syncthreads();
        if (t + NSTG < DPG) {
            if (tid == 0)
                asm volatile("fence.proxy.async.shared::cta;" ::: "memory");
            ISSUE(t + NSTG, stage);
        }
        if (++stage == NSTG) { stage = 0; phase ^= 1; }
    }

    /* ---- epilogue: /deg, red.v2.f32 into out (holds bias) ---- */
    int r  = lane >> 2;
    int cp = (lane & 3) * 2;
#pragma unroll
    for (int m = 0; m < 2; ++m) {
        float (*acc)[4] = m ? acc1 : acc0;
        int n0 = m0 + warp * 32 + m * 16 + r;
        float dgA = (n0     < N_NODES) ? 1.0f / fmaxf(g_deg[n0], 1.0f)     : 0.f;
        float dgB = (n0 + 8 < N_NODES) ? 1.0f / fmaxf(g_deg[n0 + 8], 1.0f) : 0.f;
#pragma unroll
        for (int j = 0; j < 8; ++j) {
            int col = j * 8 + cp;
            if (n0 < N_NODES) {
                float* p = out + (size_t)n0 * FOUT + col;
                asm volatile("red.global.add.v2.f32 [%0], {%1,%2};"
                             :: "l"(p), "f"(acc[j][0] * dgA), "f"(acc[j][1] * dgA)
                             : "memory");
            }
            if (n0 + 8 < N_NODES) {
                float* p = out + (size_t)(n0 + 8) * FOUT + col;
                asm volatile("red.global.add.v2.f32 [%0], {%1,%2};"
                             :: "l"(p), "f"(acc[j][2] * dgB), "f"(acc[j][3] * dgB)
                             : "memory");
            }
        }
    }
}

/* ------------------------------------------------------------------ */
extern "C" void kernel_launch(void* const* d_in, const int* in_sizes, int n_in,
                              void* d_out, int out_size)
{
    const float* x      = (const float*)d_in[0];
    const int*   ei     = (const int*)d_in[1];
    const float* pseudo = (const float*)d_in[2];
    const float* weight = (const float*)d_in[3];   /* [126,32,64] */
    const float* bias   = (const float*)d_in[4];
    float*       out    = (float*)d_out;

    long E = (long)in_sizes[1] / 2;

    void *Tptr, *Dptr;
    cudaGetSymbolAddress(&Tptr, g_T);
    cudaGetSymbolAddress(&Dptr, g_deg);

    /* unconditional, capture-safe (not a stream op) */
    cudaFuncSetAttribute(gemm_kernel,
                         cudaFuncAttributeMaxDynamicSharedMemorySize, GEMM_SMEM);

    /* repack weights (tiny) */
    wfrag_kernel<<<(NCHUNK * 2 * 8 * 32 + 255) / 256, 256>>>(weight);

    /* out = bias (GEMM reds accumulate onto it) */
    biasinit_kernel<<<(N_NODES * FOUT / 4 + 255) / 256, 256>>>(bias, out);

    /* zero T (incl. pad) and deg */
    cudaMemsetAsync(Tptr, 0, T_HALFS * sizeof(__half), 0);
    cudaMemsetAsync(Dptr, 0, (size_t)N_NODES * sizeof(float), 0);

    /* scatter */
    {
        long threads = E * 4;
        int blocks = (int)((threads + 255) / 256);
        scatter_kernel<<<blocks, 256>>>(x, ei, pseudo, E);
    }

    /* root chunk: x * deg */
    rootfill_kernel<<<(N_NODES * 4 + 255) / 256, 256>>>(x);

    /* split-K GEMM, reds directly into out */
    {
        dim3 grid((N_NODES + BM - 1) / BM, KSPLIT);
        gemm_kernel<<<grid, 128, GEMM_SMEM>>>(out);
    }
}